// round 1
// baseline (speedup 1.0000x reference)
#include <cuda_runtime.h>
#include <math.h>

// Problem constants (fixed shapes per metadata: y_s, y_t : [4, 256, 32000] fp32)
#define B 4
#define S 256
#define V 32000
#define BS (B * S)            // 1024 rows per tensor
#define KSPLIT 25
#define KCHUNK (V / KSPLIT)   // 1280
#define BM 64
#define BN 64
#define BK 32

// ---------------- device scratch (static; no runtime allocation) ----------------
__device__ float g_prob[2][BS * V];            // normalized softmax probabilities (262 MB)
__device__ float g_m[2 * BS];                  // per-row max of y*0.5
__device__ float g_rz[2 * BS];                 // per-row 1/Z
__device__ float g_part[B * KSPLIT * S * S];   // K-split partial sum-of-min (26 MB)
__device__ float g_W[B * S * S];               // L1 cost matrices
__device__ float g_P[B * S * S];               // Sinkhorn transport plan
__device__ float g_loss[B];                    // per-batch loss

// ---------------- phase 1: per-row online softmax stats (max, 1/Z) ----------------
__global__ void stats_kernel(const float* __restrict__ ys, const float* __restrict__ yt) {
    int row = blockIdx.x;          // 0..BS-1
    int tensor = blockIdx.y;       // 0 = ys, 1 = yt
    const float* y = (tensor ? yt : ys) + (size_t)row * V;
    int tid = threadIdx.x;

    float m = -INFINITY, Z = 0.f;
    for (int k = tid; k < V; k += 256) {
        float x = y[k] * 0.5f;     // y / TEMP
        if (x > m) { Z = Z * expf(m - x) + 1.0f; m = x; }
        else       { Z += expf(x - m); }
    }

    __shared__ float sm[256], sz[256];
    sm[tid] = m; sz[tid] = Z;
    __syncthreads();
    for (int s = 128; s > 0; s >>= 1) {
        if (tid < s) {
            float m1 = sm[tid], z1 = sz[tid];
            float m2 = sm[tid + s], z2 = sz[tid + s];
            float M = fmaxf(m1, m2);
            sz[tid] = z1 * expf(m1 - M) + z2 * expf(m2 - M);
            sm[tid] = M;
        }
        __syncthreads();
    }
    if (tid == 0) {
        int out = tensor * BS + row;
        g_m[out]  = sm[0];
        g_rz[out] = 1.0f / sz[0];
    }
}

// ---------------- phase 2: materialize normalized probabilities ----------------
__global__ void convert_kernel(const float* __restrict__ ys, const float* __restrict__ yt) {
    int tensor = blockIdx.y;
    int f = blockIdx.x * 256 + threadIdx.x;          // float4 index < BS*V/4
    const float* y = tensor ? yt : ys;
    int row = f / (V / 4);
    float m = g_m[tensor * BS + row];
    float r = g_rz[tensor * BS + row];
    float4 v = ((const float4*)y)[f];
    float4 o;
    o.x = expf(v.x * 0.5f - m) * r;
    o.y = expf(v.y * 0.5f - m) * r;
    o.z = expf(v.z * 0.5f - m) * r;
    o.w = expf(v.w * 0.5f - m) * r;
    ((float4*)g_prob[tensor])[f] = o;
}

// ---------------- phase 3: sum-of-min "GEMM" (L1 cdist via 2 - 2*summin) ----------------
// Grid: (16 tiles [it*4+jt], KSPLIT, B). 256 threads, 64x64 tile, 4x4 micro-tile.
__global__ void __launch_bounds__(256) cdist_kernel() {
    __shared__ float sa[BK][BM + 4];   // K-major, pad 4 keeps float4 alignment + spreads banks
    __shared__ float sb[BK][BN + 4];

    int t  = threadIdx.x;
    int it = blockIdx.x >> 2;
    int jt = blockIdx.x & 3;
    int ks = blockIdx.y;
    int b  = blockIdx.z;

    const float* A  = g_prob[0] + ((size_t)(b * S + it * BM)) * V + ks * KCHUNK;
    const float* Bp = g_prob[1] + ((size_t)(b * S + jt * BN)) * V + ks * KCHUNK;

    int tx = t & 15;      // j-group (4 cols)
    int ty = t >> 4;      // i-group (4 rows)
    int lr = t >> 3;      // loader row 0..31
    int lk = (t & 7) << 2; // loader k offset 0,4,...,28

    float acc[4][4];
#pragma unroll
    for (int i = 0; i < 4; i++)
#pragma unroll
        for (int j = 0; j < 4; j++) acc[i][j] = 0.f;

    for (int kb = 0; kb < KCHUNK; kb += BK) {
#pragma unroll
        for (int p = 0; p < 2; p++) {
            int rr = lr + p * 32;
            float4 va = *(const float4*)(A  + (size_t)rr * V + kb + lk);
            sa[lk + 0][rr] = va.x; sa[lk + 1][rr] = va.y;
            sa[lk + 2][rr] = va.z; sa[lk + 3][rr] = va.w;
            float4 vb = *(const float4*)(Bp + (size_t)rr * V + kb + lk);
            sb[lk + 0][rr] = vb.x; sb[lk + 1][rr] = vb.y;
            sb[lk + 2][rr] = vb.z; sb[lk + 3][rr] = vb.w;
        }
        __syncthreads();

#pragma unroll
        for (int kk = 0; kk < BK; kk++) {
            float4 av = *(const float4*)&sa[kk][ty << 2];
            float4 bv = *(const float4*)&sb[kk][tx << 2];
            float a[4] = {av.x, av.y, av.z, av.w};
            float c[4] = {bv.x, bv.y, bv.z, bv.w};
#pragma unroll
            for (int i = 0; i < 4; i++)
#pragma unroll
                for (int j = 0; j < 4; j++)
                    acc[i][j] += fminf(a[i], c[j]);   // FMNMX (alu) + FADD (fma): dual-issue
        }
        __syncthreads();
    }

    float* out = g_part + ((size_t)(b * KSPLIT + ks)) * (S * S)
               + (it * BM + (ty << 2)) * S + jt * BN + (tx << 2);
#pragma unroll
    for (int i = 0; i < 4; i++)
        *(float4*)(out + i * S) = make_float4(acc[i][0], acc[i][1], acc[i][2], acc[i][3]);
}

// ---------------- phase 4: deterministic K-split reduction -> W = 2 - 2*summin ----------------
__global__ void reduceW_kernel() {
    int idx = blockIdx.x * 256 + threadIdx.x;    // < B*S*S
    int b  = idx >> 16;
    int ij = idx & 65535;
    float s = 0.f;
#pragma unroll
    for (int ks = 0; ks < KSPLIT; ks++)
        s += g_part[(size_t)(b * KSPLIT + ks) * (S * S) + ij];
    g_W[idx] = 2.0f - 2.0f * s;
}

// ---------------- phase 5: Sinkhorn iterations + loss (one block per batch) ----------------
__global__ void __launch_bounds__(1024) sinkhorn_kernel() {
    int b = blockIdx.x, tid = threadIdx.x;
    const float* W = g_W + (size_t)b * (S * S);
    float* P = g_P + (size_t)b * (S * S);

    __shared__ float srow[256], scol[256], spart[4 * 256];
    __shared__ float red[32];

    for (int idx = tid; idx < S * S; idx += 1024)
        P[idx] = expf(-10.0f * W[idx]);           // -W / EPS, EPS = 0.1
    __syncthreads();

    int lane = tid & 31, w = tid >> 5;
    int j = tid & 255, q = tid >> 8;

    for (int it = 0; it < 10; it++) {
        // row sums: warp-per-row, lane-strided
        for (int i = w; i < 256; i += 32) {
            float s = 0.f;
            for (int jj = lane; jj < 256; jj += 32) s += P[i * 256 + jj];
#pragma unroll
            for (int o = 16; o; o >>= 1) s += __shfl_xor_sync(0xffffffffu, s, o);
            if (lane == 0) srow[i] = s;
        }
        __syncthreads();
        for (int idx = tid; idx < S * S; idx += 1024)
            P[idx] = P[idx] / srow[idx >> 8];
        __syncthreads();

        // col sums: thread per (quarter, col)
        {
            float s = 0.f;
            int i0 = q * 64;
            for (int i = i0; i < i0 + 64; i++) s += P[i * 256 + j];
            spart[q * 256 + j] = s;
        }
        __syncthreads();
        if (tid < 256)
            scol[tid] = spart[tid] + spart[256 + tid] + spart[512 + tid] + spart[768 + tid];
        __syncthreads();
        for (int idx = tid; idx < S * S; idx += 1024)
            P[idx] = P[idx] / scol[idx & 255];
        __syncthreads();
    }

    float acc = 0.f;
    for (int idx = tid; idx < S * S; idx += 1024) acc += P[idx] * W[idx];
#pragma unroll
    for (int o = 16; o; o >>= 1) acc += __shfl_xor_sync(0xffffffffu, acc, o);
    if (lane == 0) red[w] = acc;
    __syncthreads();
    if (tid == 0) {
        float s = 0.f;
        for (int k = 0; k < 32; k++) s += red[k];
        g_loss[b] = s;
    }
}

__global__ void finalize_kernel(float* out) {
    out[0] = 0.001f * (g_loss[0] + g_loss[1] + g_loss[2] + g_loss[3]);
}

// ---------------- launch ----------------
extern "C" void kernel_launch(void* const* d_in, const int* in_sizes, int n_in,
                              void* d_out, int out_size) {
    const float* ys = (const float*)d_in[0];
    const float* yt = (const float*)d_in[1];

    stats_kernel<<<dim3(BS, 2), 256>>>(ys, yt);
    convert_kernel<<<dim3(BS * V / 1024, 2), 256>>>(ys, yt);   // 1 float4 per thread
    cdist_kernel<<<dim3(16, KSPLIT, B), 256>>>();
    reduceW_kernel<<<dim3(B * S * S / 256), 256>>>();
    sinkhorn_kernel<<<B, 1024>>>();
    finalize_kernel<<<1, 1>>>((float*)d_out);
}

// round 2
// speedup vs baseline: 1.8398x; 1.8398x over previous
#include <cuda_runtime.h>
#include <cuda_fp16.h>
#include <math.h>

// Fixed shapes: y_s, y_t : [4, 256, 32000] fp32
#define B 4
#define S 256
#define V 32000
#define BS (B * S)            // 1024 rows per tensor
#define KSPLIT 25
#define KCHUNK (V / KSPLIT)   // 1280 halfs per chunk
#define BM 64
#define BN 64
#define BK2 32                // half2 per smem stage (= 64 elements)
#define NSTAGE (KCHUNK / (2 * BK2))   // 20
#define SCALE 8192.0f
#define INV2SCALE (2.0f / SCALE)

// ---------------- static device scratch ----------------
__device__ __half g_probh[2][BS * V];          // scaled softmax probs (131 MB)
__device__ float g_m[2 * BS];
__device__ float g_rz[2 * BS];
__device__ float g_part[B * KSPLIT * S * S];   // K-split partial scaled sum-of-min
__device__ float g_W[B * S * S];
__device__ float g_P[B * S * S];
__device__ float g_loss[B];

// ---------------- phase 1: per-row online softmax stats ----------------
__global__ void stats_kernel(const float* __restrict__ ys, const float* __restrict__ yt) {
    int row = blockIdx.x;
    int tensor = blockIdx.y;
    const float* y = (tensor ? yt : ys) + (size_t)row * V;
    int tid = threadIdx.x;

    float m = -INFINITY, Z = 0.f;
    for (int k = tid; k < V; k += 256) {
        float x = y[k] * 0.5f;                 // y / TEMP
        if (x > m) { Z = Z * __expf(m - x) + 1.0f; m = x; }
        else       { Z += __expf(x - m); }
    }

    __shared__ float sm[256], sz[256];
    sm[tid] = m; sz[tid] = Z;
    __syncthreads();
    for (int s = 128; s > 0; s >>= 1) {
        if (tid < s) {
            float m1 = sm[tid], z1 = sz[tid];
            float m2 = sm[tid + s], z2 = sz[tid + s];
            float M = fmaxf(m1, m2);
            sz[tid] = z1 * __expf(m1 - M) + z2 * __expf(m2 - M);
            sm[tid] = M;
        }
        __syncthreads();
    }
    if (tid == 0) {
        int out = tensor * BS + row;
        g_m[out]  = sm[0];
        g_rz[out] = 1.0f / sz[0];
    }
}

// ---------------- phase 2: materialize scaled probs as half ----------------
__global__ void convert_kernel(const float* __restrict__ ys, const float* __restrict__ yt) {
    int tensor = blockIdx.y;
    int g = blockIdx.x * 256 + threadIdx.x;    // 8-float group, < BS*V/8
    const float* y = tensor ? yt : ys;
    int row = g / (V / 8);                     // V/8 = 4000
    float m = g_m[tensor * BS + row];
    float r = g_rz[tensor * BS + row] * SCALE;
    const float4* y4 = (const float4*)y;
    float4 v0 = y4[2 * g], v1 = y4[2 * g + 1];
    __half2 h[4];
    h[0] = __floats2half2_rn(__expf(v0.x * 0.5f - m) * r, __expf(v0.y * 0.5f - m) * r);
    h[1] = __floats2half2_rn(__expf(v0.z * 0.5f - m) * r, __expf(v0.w * 0.5f - m) * r);
    h[2] = __floats2half2_rn(__expf(v1.x * 0.5f - m) * r, __expf(v1.y * 0.5f - m) * r);
    h[3] = __floats2half2_rn(__expf(v1.z * 0.5f - m) * r, __expf(v1.w * 0.5f - m) * r);
    ((uint4*)g_probh[tensor])[g] = *(uint4*)h;
}

// ---------------- phase 3: half2 sum-of-min "GEMM" ----------------
// Grid (16, KSPLIT, B). 256 threads, 64x64 tile, 4x4 micro-tile, HMNMX2+HADD2 inner.
__global__ void __launch_bounds__(256, 2) cdist_kernel() {
    __shared__ __align__(16) __half2 sa2[BK2][BM + 4];   // row stride 272B (16B mult)
    __shared__ __align__(16) __half2 sb2[BK2][BN + 4];

    int t  = threadIdx.x;
    int it = blockIdx.x >> 2;
    int jt = blockIdx.x & 3;
    int ks = blockIdx.y;
    int b  = blockIdx.z;

    const __half* A  = g_probh[0] + (size_t)(b * S + it * BM) * V + ks * KCHUNK;
    const __half* Bp = g_probh[1] + (size_t)(b * S + jt * BN) * V + ks * KCHUNK;

    int tx = t & 15;          // j-group
    int ty = t >> 4;          // i-group
    int lrow = t >> 2;        // loader row 0..63
    int lq   = t & 3;         // loader quarter

    const uint4* pa4 = (const uint4*)(A  + (size_t)lrow * V);   // 8 uint4 per stage row
    const uint4* pb4 = (const uint4*)(Bp + (size_t)lrow * V);

    uint4 ra0 = pa4[lq], ra1 = pa4[lq + 4];
    uint4 rb0 = pb4[lq], rb1 = pb4[lq + 4];

    float acc[4][4];
#pragma unroll
    for (int i = 0; i < 4; i++)
#pragma unroll
        for (int j = 0; j < 4; j++) acc[i][j] = 0.f;

    for (int s = 0; s < NSTAGE; s++) {
        __syncthreads();
        {
            const __half2* p0 = (const __half2*)&ra0;
            const __half2* p1 = (const __half2*)&ra1;
            const __half2* q0 = (const __half2*)&rb0;
            const __half2* q1 = (const __half2*)&rb1;
#pragma unroll
            for (int j = 0; j < 4; j++) {
                sa2[lq * 4 + j][lrow]      = p0[j];
                sa2[lq * 4 + 16 + j][lrow] = p1[j];
                sb2[lq * 4 + j][lrow]      = q0[j];
                sb2[lq * 4 + 16 + j][lrow] = q1[j];
            }
        }
        __syncthreads();
        if (s + 1 < NSTAGE) {
            int base = (s + 1) * 8;
            ra0 = pa4[base + lq]; ra1 = pa4[base + lq + 4];
            rb0 = pb4[base + lq]; rb1 = pb4[base + lq + 4];
        }

        __half2 hacc[4][4];
#pragma unroll
        for (int i = 0; i < 4; i++)
#pragma unroll
            for (int j = 0; j < 4; j++) hacc[i][j] = __float2half2_rn(0.f);

#pragma unroll
        for (int kk2 = 0; kk2 < BK2; kk2++) {
            float4 fa = *(const float4*)&sa2[kk2][ty << 2];
            float4 fb = *(const float4*)&sb2[kk2][tx << 2];
            const __half2* a2 = (const __half2*)&fa;
            const __half2* b2 = (const __half2*)&fb;
#pragma unroll
            for (int i = 0; i < 4; i++)
#pragma unroll
                for (int j = 0; j < 4; j++)
                    hacc[i][j] = __hadd2(hacc[i][j], __hmin2(a2[i], b2[j]));
        }
#pragma unroll
        for (int i = 0; i < 4; i++)
#pragma unroll
            for (int j = 0; j < 4; j++) {
                float2 f = __half22float2(hacc[i][j]);
                acc[i][j] += f.x + f.y;
            }
    }

    float* out = g_part + (size_t)(b * KSPLIT + ks) * (S * S)
               + (it * BM + (ty << 2)) * S + jt * BN + (tx << 2);
#pragma unroll
    for (int i = 0; i < 4; i++)
        *(float4*)(out + i * S) = make_float4(acc[i][0], acc[i][1], acc[i][2], acc[i][3]);
}

// ---------------- phase 4: K-split reduce -> W = 2 - 2*summin ----------------
__global__ void reduceW_kernel() {
    int idx = blockIdx.x * 256 + threadIdx.x;
    int b  = idx >> 16;
    int ij = idx & 65535;
    float s = 0.f;
#pragma unroll
    for (int ks = 0; ks < KSPLIT; ks++)
        s += g_part[(size_t)(b * KSPLIT + ks) * (S * S) + ij];
    g_W[idx] = 2.0f - s * INV2SCALE;
}

// ---------------- phase 5: Sinkhorn (warp-owns-8-rows, fused passes) ----------------
__global__ void __launch_bounds__(1024) sinkhorn_kernel() {
    int b = blockIdx.x, t = threadIdx.x;
    int w = t >> 5, lane = t & 31;
    const float* W = g_W + (size_t)b * (S * S);
    float* P = g_P + (size_t)b * (S * S);

    __shared__ float srinv[256];
    __shared__ float scinv[256];
    __shared__ float cpart[32][256];
    __shared__ float spart[4][256];
    __shared__ float red[32];

    // init: P = exp(-10W), row sums
#pragma unroll
    for (int r = 0; r < 8; r++) {
        int row = w * 8 + r;
        float4 w0 = ((const float4*)(W + row * 256))[lane];
        float4 w1 = ((const float4*)(W + row * 256))[lane + 32];
        float4 p0, p1;
        p0.x = __expf(-10.f * w0.x); p0.y = __expf(-10.f * w0.y);
        p0.z = __expf(-10.f * w0.z); p0.w = __expf(-10.f * w0.w);
        p1.x = __expf(-10.f * w1.x); p1.y = __expf(-10.f * w1.y);
        p1.z = __expf(-10.f * w1.z); p1.w = __expf(-10.f * w1.w);
        ((float4*)(P + row * 256))[lane] = p0;
        ((float4*)(P + row * 256))[lane + 32] = p1;
        float rs = p0.x + p0.y + p0.z + p0.w + p1.x + p1.y + p1.z + p1.w;
#pragma unroll
        for (int o = 16; o; o >>= 1) rs += __shfl_xor_sync(0xffffffffu, rs, o);
        if (lane == 0) srinv[row] = 1.0f / rs;
    }
    __syncthreads();

    for (int iter = 0; iter < 10; iter++) {
        // pass A: row-divide, accumulate column partials
        float4 c0 = make_float4(0, 0, 0, 0), c1 = make_float4(0, 0, 0, 0);
#pragma unroll
        for (int r = 0; r < 8; r++) {
            int row = w * 8 + r;
            float ri = srinv[row];
            float4 x0 = ((float4*)(P + row * 256))[lane];
            float4 x1 = ((float4*)(P + row * 256))[lane + 32];
            x0.x *= ri; x0.y *= ri; x0.z *= ri; x0.w *= ri;
            x1.x *= ri; x1.y *= ri; x1.z *= ri; x1.w *= ri;
            ((float4*)(P + row * 256))[lane] = x0;
            ((float4*)(P + row * 256))[lane + 32] = x1;
            c0.x += x0.x; c0.y += x0.y; c0.z += x0.z; c0.w += x0.w;
            c1.x += x1.x; c1.y += x1.y; c1.z += x1.z; c1.w += x1.w;
        }
        ((float4*)cpart[w])[lane] = c0;
        ((float4*)cpart[w])[lane + 32] = c1;
        __syncthreads();
        {
            int c = t & 255, g = t >> 8;
            float s = 0.f;
#pragma unroll
            for (int k = 0; k < 8; k++) s += cpart[g * 8 + k][c];
            spart[g][c] = s;
        }
        __syncthreads();
        if (t < 256)
            scinv[t] = 1.0f / (spart[0][t] + spart[1][t] + spart[2][t] + spart[3][t]);
        __syncthreads();

        // pass B: col-divide, accumulate row sums for next iter
        float4 d0 = ((float4*)scinv)[lane];
        float4 d1 = ((float4*)scinv)[lane + 32];
#pragma unroll
        for (int r = 0; r < 8; r++) {
            int row = w * 8 + r;
            float4 x0 = ((float4*)(P + row * 256))[lane];
            float4 x1 = ((float4*)(P + row * 256))[lane + 32];
            x0.x *= d0.x; x0.y *= d0.y; x0.z *= d0.z; x0.w *= d0.w;
            x1.x *= d1.x; x1.y *= d1.y; x1.z *= d1.z; x1.w *= d1.w;
            ((float4*)(P + row * 256))[lane] = x0;
            ((float4*)(P + row * 256))[lane + 32] = x1;
            float rs = x0.x + x0.y + x0.z + x0.w + x1.x + x1.y + x1.z + x1.w;
#pragma unroll
            for (int o = 16; o; o >>= 1) rs += __shfl_xor_sync(0xffffffffu, rs, o);
            if (lane == 0) srinv[row] = 1.0f / rs;
        }
        __syncthreads();
    }

    // loss = sum(P * W)
    float acc = 0.f;
#pragma unroll
    for (int r = 0; r < 8; r++) {
        int row = w * 8 + r;
        float4 p0 = ((const float4*)(P + row * 256))[lane];
        float4 p1 = ((const float4*)(P + row * 256))[lane + 32];
        float4 w0 = ((const float4*)(W + row * 256))[lane];
        float4 w1 = ((const float4*)(W + row * 256))[lane + 32];
        acc += p0.x * w0.x + p0.y * w0.y + p0.z * w0.z + p0.w * w0.w
             + p1.x * w1.x + p1.y * w1.y + p1.z * w1.z + p1.w * w1.w;
    }
#pragma unroll
    for (int o = 16; o; o >>= 1) acc += __shfl_xor_sync(0xffffffffu, acc, o);
    if (lane == 0) red[w] = acc;
    __syncthreads();
    if (t == 0) {
        float s = 0.f;
        for (int k = 0; k < 32; k++) s += red[k];
        g_loss[b] = s;
    }
}

__global__ void finalize_kernel(float* out) {
    out[0] = 0.001f * (g_loss[0] + g_loss[1] + g_loss[2] + g_loss[3]);
}

// ---------------- launch ----------------
extern "C" void kernel_launch(void* const* d_in, const int* in_sizes, int n_in,
                              void* d_out, int out_size) {
    const float* ys = (const float*)d_in[0];
    const float* yt = (const float*)d_in[1];

    stats_kernel<<<dim3(BS, 2), 256>>>(ys, yt);
    convert_kernel<<<dim3(BS * V / 8 / 256, 2), 256>>>(ys, yt);
    cdist_kernel<<<dim3(16, KSPLIT, B), 256>>>();
    reduceW_kernel<<<dim3(B * S * S / 256), 256>>>();
    sinkhorn_kernel<<<B, 1024>>>();
    finalize_kernel<<<1, 1>>>((float*)d_out);
}

// round 4
// speedup vs baseline: 1.9732x; 1.0725x over previous
#include <cuda_runtime.h>
#include <cuda_fp16.h>
#include <math.h>

// Fixed shapes: y_s, y_t : [4, 256, 32000] fp32
#define B 4
#define S 256
#define V 32000
#define BS (B * S)
#define KSPLIT 25
#define KCHUNK (V / KSPLIT)        // 1280 halfs
#define BM 128
#define BN 64
#define BK2 32                     // half2 per stage = 64 halfs
#define NSTAGE (KCHUNK / 64)       // 20
#define SCALE 8192.0f
#define INV2SCALE (2.0f / SCALE)

// ---------------- static device scratch ----------------
__device__ __half g_probe[2][BS * V];          // UNNORMALIZED exp(y/2) as half (131 MB)
__device__ __half2 g_rzh[2 * BS];              // per-row SCALE/Z as half2
__device__ float g_part[B * KSPLIT * S * S];   // K-split partial scaled sum-of-min
__device__ float g_W[B * S * S];
__device__ float g_P[B * S * S];
__device__ float g_loss[B];

// ---------------- phase 1 (fused): exp + row-sum stats, single pass over y ----------------
__global__ void stats_kernel(const float* __restrict__ ys, const float* __restrict__ yt) {
    int row = blockIdx.x;
    int tensor = blockIdx.y;
    const float* y = (tensor ? yt : ys) + (size_t)row * V;
    __half* e = g_probe[tensor] + (size_t)row * V;
    int tid = threadIdx.x;

    float Z = 0.f;
    for (int f = tid; f < V / 4; f += 256) {
        float4 v = ((const float4*)y)[f];
        float e0 = __expf(v.x * 0.5f);
        float e1 = __expf(v.y * 0.5f);
        float e2 = __expf(v.z * 0.5f);
        float e3 = __expf(v.w * 0.5f);
        Z += (e0 + e1) + (e2 + e3);
        __half2 h[2];
        h[0] = __floats2half2_rn(e0, e1);
        h[1] = __floats2half2_rn(e2, e3);
        ((uint2*)e)[f] = *(uint2*)h;
    }

    __shared__ float sz[256];
    sz[tid] = Z;
    __syncthreads();
    for (int s = 128; s > 0; s >>= 1) {
        if (tid < s) sz[tid] += sz[tid + s];
        __syncthreads();
    }
    if (tid == 0) {
        float r = SCALE / sz[0];
        g_rzh[tensor * BS + row] = __floats2half2_rn(r, r);
    }
}

// ---------------- phase 2: half2 sum-of-min "GEMM", 128x64 tile, 8x4 micro ----------------
__global__ void __launch_bounds__(256, 2) cdist_kernel() {
    __shared__ __align__(16) __half2 sa2[BK2][BM + 4];
    __shared__ __align__(16) __half2 sb2[BK2][BN + 4];

    int t  = threadIdx.x;
    int it = blockIdx.x >> 2;      // 0..1
    int jt = blockIdx.x & 3;       // 0..3
    int ks = blockIdx.y;
    int b  = blockIdx.z;

    const __half* A  = g_probe[0] + (size_t)(b * S + it * BM) * V + ks * KCHUNK;
    const __half* Bp = g_probe[1] + (size_t)(b * S + jt * BN) * V + ks * KCHUNK;

    // loaders: A row = t&127 (2 thread-groups by t>>7, 4 uint4 each)
    //          B row = t&63  (4 thread-groups by t>>6, 2 uint4 each)
    int arow = t & 127, aq = t >> 7;
    int brow = t & 63,  bq = t >> 6;
    const uint4* pa = (const uint4*)(A  + (size_t)arow * V);
    const uint4* pb = (const uint4*)(Bp + (size_t)brow * V);
    __half2 ra = g_rzh[b * S + it * BM + arow];
    __half2 rb = g_rzh[BS + b * S + jt * BN + brow];

    // compute mapping: 8 rows x 4 cols per thread
    int tx = t & 15;               // col group
    int ty = t >> 4;               // row group

    uint4 ga[4], gb[2];
#pragma unroll
    for (int u = 0; u < 4; u++) ga[u] = pa[aq * 4 + u];
#pragma unroll
    for (int u = 0; u < 2; u++) gb[u] = pb[bq * 2 + u];

    float acc[8][4];
#pragma unroll
    for (int i = 0; i < 8; i++)
#pragma unroll
        for (int j = 0; j < 4; j++) acc[i][j] = 0.f;

    for (int s = 0; s < NSTAGE; s++) {
        __syncthreads();
#pragma unroll
        for (int u = 0; u < 4; u++) {
            const __half2* h = (const __half2*)&ga[u];
#pragma unroll
            for (int j = 0; j < 4; j++)
                sa2[(aq * 4 + u) * 4 + j][arow] = __hmul2(h[j], ra);
        }
#pragma unroll
        for (int u = 0; u < 2; u++) {
            const __half2* h = (const __half2*)&gb[u];
#pragma unroll
            for (int j = 0; j < 4; j++)
                sb2[(bq * 2 + u) * 4 + j][brow] = __hmul2(h[j], rb);
        }
        __syncthreads();
        if (s + 1 < NSTAGE) {
            int base = (s + 1) * 8;
#pragma unroll
            for (int u = 0; u < 4; u++) ga[u] = pa[base + aq * 4 + u];
#pragma unroll
            for (int u = 0; u < 2; u++) gb[u] = pb[base + bq * 2 + u];
        }

        __half2 hacc[8][4];
#pragma unroll
        for (int i = 0; i < 8; i++)
#pragma unroll
            for (int j = 0; j < 4; j++) hacc[i][j] = __float2half2_rn(0.f);

#pragma unroll
        for (int kk2 = 0; kk2 < BK2; kk2++) {
            float4 fa0 = *(const float4*)&sa2[kk2][ty * 8];
            float4 fa1 = *(const float4*)&sa2[kk2][ty * 8 + 4];
            float4 fb  = *(const float4*)&sb2[kk2][tx * 4];
            const __half2* a0 = (const __half2*)&fa0;
            const __half2* a1 = (const __half2*)&fa1;
            const __half2* bb = (const __half2*)&fb;
#pragma unroll
            for (int i = 0; i < 4; i++)
#pragma unroll
                for (int j = 0; j < 4; j++) {
                    hacc[i][j]     = __hadd2(hacc[i][j],     __hmin2(a0[i], bb[j]));
                    hacc[i + 4][j] = __hadd2(hacc[i + 4][j], __hmin2(a1[i], bb[j]));
                }
        }
#pragma unroll
        for (int i = 0; i < 8; i++)
#pragma unroll
            for (int j = 0; j < 4; j++) {
                float2 f = __half22float2(hacc[i][j]);
                acc[i][j] += f.x + f.y;
            }
    }

    float* out = g_part + (size_t)(b * KSPLIT + ks) * (S * S)
               + (it * BM + ty * 8) * S + jt * BN + tx * 4;
#pragma unroll
    for (int i = 0; i < 8; i++)
        *(float4*)(out + i * S) = make_float4(acc[i][0], acc[i][1], acc[i][2], acc[i][3]);
}

// ---------------- phase 3: K-split reduce -> W = 2 - 2*summin ----------------
__global__ void reduceW_kernel() {
    int idx = blockIdx.x * 256 + threadIdx.x;
    int b  = idx >> 16;
    int ij = idx & 65535;
    float s = 0.f;
#pragma unroll
    for (int ks = 0; ks < KSPLIT; ks++)
        s += g_part[(size_t)(b * KSPLIT + ks) * (S * S) + ij];
    g_W[idx] = 2.0f - s * INV2SCALE;
}

// ---------------- phase 4: Sinkhorn (warp-owns-8-rows, fused passes) ----------------
__global__ void __launch_bounds__(1024) sinkhorn_kernel() {
    int b = blockIdx.x, t = threadIdx.x;
    int w = t >> 5, lane = t & 31;
    const float* W = g_W + (size_t)b * (S * S);
    float* P = g_P + (size_t)b * (S * S);

    __shared__ float srinv[256];
    __shared__ float scinv[256];
    __shared__ float cpart[32][256];
    __shared__ float spart[4][256];
    __shared__ float red[32];

#pragma unroll
    for (int r = 0; r < 8; r++) {
        int row = w * 8 + r;
        float4 w0 = ((const float4*)(W + row * 256))[lane];
        float4 w1 = ((const float4*)(W + row * 256))[lane + 32];
        float4 p0, p1;
        p0.x = __expf(-10.f * w0.x); p0.y = __expf(-10.f * w0.y);
        p0.z = __expf(-10.f * w0.z); p0.w = __expf(-10.f * w0.w);
        p1.x = __expf(-10.f * w1.x); p1.y = __expf(-10.f * w1.y);
        p1.z = __expf(-10.f * w1.z); p1.w = __expf(-10.f * w1.w);
        ((float4*)(P + row * 256))[lane] = p0;
        ((float4*)(P + row * 256))[lane + 32] = p1;
        float rs = p0.x + p0.y + p0.z + p0.w + p1.x + p1.y + p1.z + p1.w;
#pragma unroll
        for (int o = 16; o; o >>= 1) rs += __shfl_xor_sync(0xffffffffu, rs, o);
        if (lane == 0) srinv[row] = 1.0f / rs;
    }
    __syncthreads();

    for (int iter = 0; iter < 10; iter++) {
        float4 c0 = make_float4(0, 0, 0, 0), c1 = make_float4(0, 0, 0, 0);
#pragma unroll
        for (int r = 0; r < 8; r++) {
            int row = w * 8 + r;
            float ri = srinv[row];
            float4 x0 = ((float4*)(P + row * 256))[lane];
            float4 x1 = ((float4*)(P + row * 256))[lane + 32];
            x0.x *= ri; x0.y *= ri; x0.z *= ri; x0.w *= ri;
            x1.x *= ri; x1.y *= ri; x1.z *= ri; x1.w *= ri;
            ((float4*)(P + row * 256))[lane] = x0;
            ((float4*)(P + row * 256))[lane + 32] = x1;
            c0.x += x0.x; c0.y += x0.y; c0.z += x0.z; c0.w += x0.w;
            c1.x += x1.x; c1.y += x1.y; c1.z += x1.z; c1.w += x1.w;
        }
        ((float4*)cpart[w])[lane] = c0;
        ((float4*)cpart[w])[lane + 32] = c1;
        __syncthreads();
        {
            int c = t & 255, g = t >> 8;
            float s = 0.f;
#pragma unroll
            for (int k = 0; k < 8; k++) s += cpart[g * 8 + k][c];
            spart[g][c] = s;
        }
        __syncthreads();
        if (t < 256)
            scinv[t] = 1.0f / (spart[0][t] + spart[1][t] + spart[2][t] + spart[3][t]);
        __syncthreads();

        float4 d0 = ((float4*)scinv)[lane];
        float4 d1 = ((float4*)scinv)[lane + 32];
#pragma unroll
        for (int r = 0; r < 8; r++) {
            int row = w * 8 + r;
            float4 x0 = ((float4*)(P + row * 256))[lane];
            float4 x1 = ((float4*)(P + row * 256))[lane + 32];
            x0.x *= d0.x; x0.y *= d0.y; x0.z *= d0.z; x0.w *= d0.w;
            x1.x *= d1.x; x1.y *= d1.y; x1.z *= d1.z; x1.w *= d1.w;
            ((float4*)(P + row * 256))[lane] = x0;
            ((float4*)(P + row * 256))[lane + 32] = x1;
            float rs = x0.x + x0.y + x0.z + x0.w + x1.x + x1.y + x1.z + x1.w;
#pragma unroll
            for (int o = 16; o; o >>= 1) rs += __shfl_xor_sync(0xffffffffu, rs, o);
            if (lane == 0) srinv[row] = 1.0f / rs;
        }
        __syncthreads();
    }

    float acc = 0.f;
#pragma unroll
    for (int r = 0; r < 8; r++) {
        int row = w * 8 + r;
        float4 p0 = ((const float4*)(P + row * 256))[lane];
        float4 p1 = ((const float4*)(P + row * 256))[lane + 32];
        float4 w0 = ((const float4*)(W + row * 256))[lane];
        float4 w1 = ((const float4*)(W + row * 256))[lane + 32];
        acc += p0.x * w0.x + p0.y * w0.y + p0.z * w0.z + p0.w * w0.w
             + p1.x * w1.x + p1.y * w1.y + p1.z * w1.z + p1.w * w1.w;
    }
#pragma unroll
    for (int o = 16; o; o >>= 1) acc += __shfl_xor_sync(0xffffffffu, acc, o);
    if (lane == 0) red[w] = acc;
    __syncthreads();
    if (t == 0) {
        float s = 0.f;
        for (int k = 0; k < 32; k++) s += red[k];
        g_loss[b] = s;
    }
}

__global__ void finalize_kernel(float* out) {
    out[0] = 0.001f * (g_loss[0] + g_loss[1] + g_loss[2] + g_loss[3]);
}

// ---------------- launch ----------------
extern "C" void kernel_launch(void* const* d_in, const int* in_sizes, int n_in,
                              void* d_out, int out_size) {
    const float* ys = (const float*)d_in[0];
    const float* yt = (const float*)d_in[1];

    stats_kernel<<<dim3(BS, 2), 256>>>(ys, yt);
    cdist_kernel<<<dim3(8, KSPLIT, B), 256>>>();
    reduceW_kernel<<<dim3(B * S * S / 256), 256>>>();
    sinkhorn_kernel<<<B, 1024>>>();
    finalize_kernel<<<1, 1>>>((float*)d_out);
}

// round 6
// speedup vs baseline: 2.1874x; 1.1086x over previous
#include <cuda_runtime.h>
#include <cuda_fp16.h>
#include <math.h>

// Fixed shapes: y_s, y_t : [4, 256, 32000] fp32
#define B 4
#define S 256
#define V 32000
#define BS (B * S)
#define KSPLIT 25
#define KCHUNK (V / KSPLIT)        // 1280 halfs
#define BM 128
#define BN 64
#define BK2 32                     // half2 per stage = 64 halfs
#define NSTAGE (KCHUNK / 64)       // 20
#define SCALE 8192.0f
#define INV2SCALE (2.0f / SCALE)

#define CD_SMEM (2 * (BK2 * (BM + 4) + BK2 * (BN + 4)) * (int)sizeof(__half2))  // 51200
#define SINK_SMEM (S * (S / 2) * (int)sizeof(__half2))                          // 131072

// ---------------- static device scratch ----------------
__device__ __half g_probe[2][BS * V];          // UNNORMALIZED exp(y/2) as half (131 MB)
__device__ __half2 g_rzh[2 * BS];              // per-row SCALE/Z as half2
__device__ float g_part[B * KSPLIT * S * S];   // K-split partial scaled sum-of-min
__device__ float g_W[B * S * S];
__device__ float g_loss[B];

// ---------------- phase 1 (fused): exp + row-sum stats, single pass over y ----------------
__global__ void stats_kernel(const float* __restrict__ ys, const float* __restrict__ yt) {
    int row = blockIdx.x;
    int tensor = blockIdx.y;
    const float* y = (tensor ? yt : ys) + (size_t)row * V;
    __half* e = g_probe[tensor] + (size_t)row * V;
    int tid = threadIdx.x;

    float Z = 0.f;
    for (int f = tid; f < V / 4; f += 256) {
        float4 v = ((const float4*)y)[f];
        float e0 = __expf(v.x * 0.5f);
        float e1 = __expf(v.y * 0.5f);
        float e2 = __expf(v.z * 0.5f);
        float e3 = __expf(v.w * 0.5f);
        Z += (e0 + e1) + (e2 + e3);
        __half2 h[2];
        h[0] = __floats2half2_rn(e0, e1);
        h[1] = __floats2half2_rn(e2, e3);
        ((uint2*)e)[f] = *(uint2*)h;
    }

    __shared__ float sz[256];
    sz[tid] = Z;
    __syncthreads();
    for (int s = 128; s > 0; s >>= 1) {
        if (tid < s) sz[tid] += sz[tid + s];
        __syncthreads();
    }
    if (tid == 0) {
        float r = SCALE / sz[0];
        g_rzh[tensor * BS + row] = __floats2half2_rn(r, r);
    }
}

// ---------------- phase 2: half2 sum-of-min "GEMM", double-buffered smem ----------------
__global__ void __launch_bounds__(256, 2) cdist_kernel() {
    extern __shared__ __align__(16) __half2 dyn[];
    typedef __half2 SA[BK2][BM + 4];
    typedef __half2 SB[BK2][BN + 4];
    SA* sa2 = (SA*)dyn;                                  // [2][BK2][BM+4]
    SB* sb2 = (SB*)(dyn + 2 * BK2 * (BM + 4));           // [2][BK2][BN+4]

    int t  = threadIdx.x;
    int it = blockIdx.x >> 2;      // 0..1
    int jt = blockIdx.x & 3;       // 0..3
    int ks = blockIdx.y;
    int b  = blockIdx.z;

    const __half* A  = g_probe[0] + (size_t)(b * S + it * BM) * V + ks * KCHUNK;
    const __half* Bp = g_probe[1] + (size_t)(b * S + jt * BN) * V + ks * KCHUNK;

    int arow = t & 127, aq = t >> 7;     // A loader: 2 groups x 4 uint4
    int brow = t & 63,  bq = t >> 6;     // B loader: 4 groups x 2 uint4
    const uint4* pa = (const uint4*)(A  + (size_t)arow * V);
    const uint4* pb = (const uint4*)(Bp + (size_t)brow * V);
    __half2 ra = g_rzh[b * S + it * BM + arow];
    __half2 rb = g_rzh[BS + b * S + jt * BN + brow];

    int tx = t & 15;               // col group (4 cols)
    int ty = t >> 4;               // row group (8 rows)

    uint4 ga[4], gb[2];
    float acc[8][4];
#pragma unroll
    for (int i = 0; i < 8; i++)
#pragma unroll
        for (int j = 0; j < 4; j++) acc[i][j] = 0.f;

    // prologue: stage 0 -> buf 0, prefetch stage 1 into regs
#pragma unroll
    for (int u = 0; u < 4; u++) ga[u] = pa[aq * 4 + u];
#pragma unroll
    for (int u = 0; u < 2; u++) gb[u] = pb[bq * 2 + u];
#pragma unroll
    for (int u = 0; u < 4; u++) {
        const __half2* h = (const __half2*)&ga[u];
#pragma unroll
        for (int j = 0; j < 4; j++)
            sa2[0][(aq * 4 + u) * 4 + j][arow] = __hmul2(h[j], ra);
    }
#pragma unroll
    for (int u = 0; u < 2; u++) {
        const __half2* h = (const __half2*)&gb[u];
#pragma unroll
        for (int j = 0; j < 4; j++)
            sb2[0][(bq * 2 + u) * 4 + j][brow] = __hmul2(h[j], rb);
    }
#pragma unroll
    for (int u = 0; u < 4; u++) ga[u] = pa[8 + aq * 4 + u];
#pragma unroll
    for (int u = 0; u < 2; u++) gb[u] = pb[8 + bq * 2 + u];
    __syncthreads();

    for (int s = 0; s < NSTAGE; s++) {
        int cur = s & 1, nxt = cur ^ 1;
        if (s + 1 < NSTAGE) {          // store regs (stage s+1) into other buffer
#pragma unroll
            for (int u = 0; u < 4; u++) {
                const __half2* h = (const __half2*)&ga[u];
#pragma unroll
                for (int j = 0; j < 4; j++)
                    sa2[nxt][(aq * 4 + u) * 4 + j][arow] = __hmul2(h[j], ra);
            }
#pragma unroll
            for (int u = 0; u < 2; u++) {
                const __half2* h = (const __half2*)&gb[u];
#pragma unroll
                for (int j = 0; j < 4; j++)
                    sb2[nxt][(bq * 2 + u) * 4 + j][brow] = __hmul2(h[j], rb);
            }
        }
        if (s + 2 < NSTAGE) {          // prefetch stage s+2 into regs
            int base = (s + 2) * 8;
#pragma unroll
            for (int u = 0; u < 4; u++) ga[u] = pa[base + aq * 4 + u];
#pragma unroll
            for (int u = 0; u < 2; u++) gb[u] = pb[base + bq * 2 + u];
        }

        __half2 hacc[8][4];
#pragma unroll
        for (int i = 0; i < 8; i++)
#pragma unroll
            for (int j = 0; j < 4; j++) hacc[i][j] = __float2half2_rn(0.f);

#pragma unroll
        for (int kk2 = 0; kk2 < BK2; kk2++) {
            float4 fa0 = *(const float4*)&sa2[cur][kk2][ty * 8];
            float4 fa1 = *(const float4*)&sa2[cur][kk2][ty * 8 + 4];
            float4 fb  = *(const float4*)&sb2[cur][kk2][tx * 4];
            const __half2* a0 = (const __half2*)&fa0;
            const __half2* a1 = (const __half2*)&fa1;
            const __half2* bb = (const __half2*)&fb;
#pragma unroll
            for (int i = 0; i < 4; i++)
#pragma unroll
                for (int j = 0; j < 4; j++) {
                    hacc[i][j]     = __hadd2(hacc[i][j],     __hmin2(a0[i], bb[j]));
                    hacc[i + 4][j] = __hadd2(hacc[i + 4][j], __hmin2(a1[i], bb[j]));
                }
        }
#pragma unroll
        for (int i = 0; i < 8; i++)
#pragma unroll
            for (int j = 0; j < 4; j++) {
                float2 f = __half22float2(hacc[i][j]);
                acc[i][j] += f.x + f.y;
            }
        __syncthreads();
    }

    float* out = g_part + (size_t)(b * KSPLIT + ks) * (S * S)
               + (it * BM + ty * 8) * S + jt * BN + tx * 4;
#pragma unroll
    for (int i = 0; i < 8; i++)
        *(float4*)(out + i * S) = make_float4(acc[i][0], acc[i][1], acc[i][2], acc[i][3]);
}

// ---------------- phase 3: K-split reduce -> W = 2 - 2*summin ----------------
__global__ void reduceW_kernel() {
    int idx = blockIdx.x * 256 + threadIdx.x;
    int b  = idx >> 16;
    int ij = idx & 65535;
    float s = 0.f;
#pragma unroll
    for (int ks = 0; ks < KSPLIT; ks++)
        s += g_part[(size_t)(b * KSPLIT + ks) * (S * S) + ij];
    g_W[idx] = 2.0f - s * INV2SCALE;
}

// ---------------- phase 4: Sinkhorn, P resident in smem as half2 ----------------
// warp w owns rows 8w..8w+7; lane l owns cols 8l..8l+7 (uint4 view: sPu[row*32+l]).
__global__ void __launch_bounds__(1024) sinkhorn_kernel() {
    extern __shared__ __align__(16) __half2 sP[];   // [256][128] half2 = 128 KB
    __shared__ float cpart[32][256];
    __shared__ float spart[4][256];
    __shared__ float scf[256];
    __shared__ float red[32];

    int b = blockIdx.x, t = threadIdx.x;
    int w = t >> 5, l = t & 31;
    const float* W = g_W + (size_t)b * (S * S);
    uint4* sPu = (uint4*)sP;

    float cp[8], rinv[8];
#pragma unroll
    for (int j = 0; j < 8; j++) cp[j] = 0.f;

    // init: e = exp(-10W), first row-normalize fully in fp32, then store half
#pragma unroll
    for (int r = 0; r < 8; r++) {
        int row = w * 8 + r;
        float4 a = ((const float4*)(W + row * 256))[2 * l];
        float4 c = ((const float4*)(W + row * 256))[2 * l + 1];
        float e[8];
        e[0] = __expf(-10.f * a.x); e[1] = __expf(-10.f * a.y);
        e[2] = __expf(-10.f * a.z); e[3] = __expf(-10.f * a.w);
        e[4] = __expf(-10.f * c.x); e[5] = __expf(-10.f * c.y);
        e[6] = __expf(-10.f * c.z); e[7] = __expf(-10.f * c.w);
        float rs = (e[0] + e[1]) + (e[2] + e[3]) + (e[4] + e[5]) + (e[6] + e[7]);
#pragma unroll
        for (int o = 16; o; o >>= 1) rs += __shfl_xor_sync(0xffffffffu, rs, o);
        float ri = 1.0f / rs;
        __half2 h[4];
#pragma unroll
        for (int j = 0; j < 4; j++) {
            float x0 = e[2 * j] * ri, x1 = e[2 * j + 1] * ri;
            cp[2 * j] += x0; cp[2 * j + 1] += x1;
            h[j] = __floats2half2_rn(x0, x1);
        }
        sPu[row * 32 + l] = *(uint4*)h;
    }

    for (int iter = 0; iter < 10; iter++) {
        // column-sum reduction from per-warp partials
        ((float4*)cpart[w])[2 * l]     = make_float4(cp[0], cp[1], cp[2], cp[3]);
        ((float4*)cpart[w])[2 * l + 1] = make_float4(cp[4], cp[5], cp[6], cp[7]);
        __syncthreads();
        {
            int c = t & 255, g = t >> 8;
            float s = 0.f;
#pragma unroll
            for (int k = 0; k < 8; k++) s += cpart[g * 8 + k][c];
            spart[g][c] = s;
        }
        __syncthreads();
        if (t < 256)
            scf[t] = 1.0f / (spart[0][t] + spart[1][t] + spart[2][t] + spart[3][t]);
        __syncthreads();

        // col multiply (fp32 math, half storage) + row sums
        float4 s0 = ((float4*)scf)[2 * l];
        float4 s1 = ((float4*)scf)[2 * l + 1];
#pragma unroll
        for (int r = 0; r < 8; r++) {
            int row = w * 8 + r;
            uint4 pu = sPu[row * 32 + l];
            __half2* ph = (__half2*)&pu;
            float2 f0 = __half22float2(ph[0]);
            float2 f1 = __half22float2(ph[1]);
            float2 f2 = __half22float2(ph[2]);
            float2 f3 = __half22float2(ph[3]);
            f0.x *= s0.x; f0.y *= s0.y; f1.x *= s0.z; f1.y *= s0.w;
            f2.x *= s1.x; f2.y *= s1.y; f3.x *= s1.z; f3.y *= s1.w;
            ph[0] = __floats2half2_rn(f0.x, f0.y);
            ph[1] = __floats2half2_rn(f1.x, f1.y);
            ph[2] = __floats2half2_rn(f2.x, f2.y);
            ph[3] = __floats2half2_rn(f3.x, f3.y);
            sPu[row * 32 + l] = pu;
            float rs = (f0.x + f0.y) + (f1.x + f1.y) + (f2.x + f2.y) + (f3.x + f3.y);
#pragma unroll
            for (int o = 16; o; o >>= 1) rs += __shfl_xor_sync(0xffffffffu, rs, o);
            rinv[r] = 1.0f / rs;
        }

        if (iter < 9) {
            // row multiply + next col partials
#pragma unroll
            for (int j = 0; j < 8; j++) cp[j] = 0.f;
#pragma unroll
            for (int r = 0; r < 8; r++) {
                int row = w * 8 + r;
                uint4 pu = sPu[row * 32 + l];
                __half2* ph = (__half2*)&pu;
                float ri = rinv[r];
                float2 f0 = __half22float2(ph[0]);
                float2 f1 = __half22float2(ph[1]);
                float2 f2 = __half22float2(ph[2]);
                float2 f3 = __half22float2(ph[3]);
                f0.x *= ri; f0.y *= ri; f1.x *= ri; f1.y *= ri;
                f2.x *= ri; f2.y *= ri; f3.x *= ri; f3.y *= ri;
                cp[0] += f0.x; cp[1] += f0.y; cp[2] += f1.x; cp[3] += f1.y;
                cp[4] += f2.x; cp[5] += f2.y; cp[6] += f3.x; cp[7] += f3.y;
                ph[0] = __floats2half2_rn(f0.x, f0.y);
                ph[1] = __floats2half2_rn(f1.x, f1.y);
                ph[2] = __floats2half2_rn(f2.x, f2.y);
                ph[3] = __floats2half2_rn(f3.x, f3.y);
                sPu[row * 32 + l] = pu;
            }
        }
        __syncthreads();
    }

    // loss = sum(P * W)
    float acc = 0.f;
#pragma unroll
    for (int r = 0; r < 8; r++) {
        int row = w * 8 + r;
        uint4 pu = sPu[row * 32 + l];
        __half2* ph = (__half2*)&pu;
        float4 a = ((const float4*)(W + row * 256))[2 * l];
        float4 c = ((const float4*)(W + row * 256))[2 * l + 1];
        float2 f0 = __half22float2(ph[0]);
        float2 f1 = __half22float2(ph[1]);
        float2 f2 = __half22float2(ph[2]);
        float2 f3 = __half22float2(ph[3]);
        acc += f0.x * a.x + f0.y * a.y + f1.x * a.z + f1.y * a.w
             + f2.x * c.x + f2.y * c.y + f3.x * c.z + f3.y * c.w;
    }
#pragma unroll
    for (int o = 16; o; o >>= 1) acc += __shfl_xor_sync(0xffffffffu, acc, o);
    if (l == 0) red[w] = acc;
    __syncthreads();
    if (t == 0) {
        float s = 0.f;
        for (int k = 0; k < 32; k++) s += red[k];
        g_loss[b] = s;
    }
}

__global__ void finalize_kernel(float* out) {
    out[0] = 0.001f * (g_loss[0] + g_loss[1] + g_loss[2] + g_loss[3]);
}

// ---------------- launch ----------------
extern "C" void kernel_launch(void* const* d_in, const int* in_sizes, int n_in,
                              void* d_out, int out_size) {
    const float* ys = (const float*)d_in[0];
    const float* yt = (const float*)d_in[1];

    cudaFuncSetAttribute(cdist_kernel, cudaFuncAttributeMaxDynamicSharedMemorySize, CD_SMEM);
    cudaFuncSetAttribute(sinkhorn_kernel, cudaFuncAttributeMaxDynamicSharedMemorySize, SINK_SMEM);

    stats_kernel<<<dim3(BS, 2), 256>>>(ys, yt);
    cdist_kernel<<<dim3(8, KSPLIT, B), 256, CD_SMEM>>>();
    reduceW_kernel<<<dim3(B * S * S / 256), 256>>>();
    sinkhorn_kernel<<<B, 1024, SINK_SMEM>>>();
    finalize_kernel<<<1, 1>>>((float*)d_out);
}

// round 7
// speedup vs baseline: 2.3642x; 1.0808x over previous
#include <cuda_runtime.h>
#include <cuda_fp16.h>
#include <math.h>

// Fixed shapes: y_s, y_t : [4, 256, 32000] fp32
#define B 4
#define S 256
#define V 32000
#define BS (B * S)
#define KS 37                      // uneven K-split: 19 chunks of 14 stages, 18 of 13 (x64 halfs)
#define BM 128
#define BN 128
#define BK2 32                     // half2 per stage = 64 halfs
#define SCALE 8192.0f
#define INV2SCALE (2.0f / SCALE)

#define CD_SMEM (2 * 2 * BK2 * (BM + 4) * (int)sizeof(__half2))   // sa+sb, double buffered: 67584
#define SINK_SMEM (S * (S / 2) * (int)sizeof(__half2))            // 131072

// ---------------- static device scratch ----------------
__device__ __half g_probe[2][BS * V];          // UNNORMALIZED exp(y/2) as half (131 MB)
__device__ __half2 g_rzh[2 * BS];              // per-row SCALE/Z as half2
__device__ float g_part[B * KS * S * S];       // K-split partial scaled sum-of-min
__device__ float g_W[B * S * S];
__device__ float g_loss[B];

// ---------------- phase 1 (fused): exp + row-sum stats, single pass over y ----------------
__global__ void stats_kernel(const float* __restrict__ ys, const float* __restrict__ yt) {
    int row = blockIdx.x;
    int tensor = blockIdx.y;
    const float* y = (tensor ? yt : ys) + (size_t)row * V;
    __half* e = g_probe[tensor] + (size_t)row * V;
    int tid = threadIdx.x;

    float Z = 0.f;
    for (int f = tid; f < V / 4; f += 256) {
        float4 v = ((const float4*)y)[f];
        float e0 = __expf(v.x * 0.5f);
        float e1 = __expf(v.y * 0.5f);
        float e2 = __expf(v.z * 0.5f);
        float e3 = __expf(v.w * 0.5f);
        Z += (e0 + e1) + (e2 + e3);
        __half2 h[2];
        h[0] = __floats2half2_rn(e0, e1);
        h[1] = __floats2half2_rn(e2, e3);
        ((uint2*)e)[f] = *(uint2*)h;
    }

    __shared__ float sz[256];
    sz[tid] = Z;
    __syncthreads();
    for (int s = 128; s > 0; s >>= 1) {
        if (tid < s) sz[tid] += sz[tid + s];
        __syncthreads();
    }
    if (tid == 0) {
        float r = SCALE / sz[0];
        g_rzh[tensor * BS + row] = __floats2half2_rn(r, r);
    }
}

// ---------------- phase 2: half2 sum-of-min "GEMM", 128x128 tile, 8x8 micro ----------------
__global__ void __launch_bounds__(256, 1) cdist_kernel() {
    extern __shared__ __align__(16) __half2 dyn[];
    typedef __half2 ST[BK2][BM + 4];
    ST* sa2 = (ST*)dyn;                         // [2][BK2][BM+4]
    ST* sb2 = (ST*)(dyn + 2 * BK2 * (BM + 4));  // [2][BK2][BN+4]

    int t  = threadIdx.x;
    int it = blockIdx.x >> 1;      // 0..1
    int jt = blockIdx.x & 1;       // 0..1
    int ks = blockIdx.y;           // 0..36
    int b  = blockIdx.z;

    int st0 = (ks < 19) ? 14 * ks : 13 * ks + 19;   // chunk start in 64-half units
    int nst = (ks < 19) ? 14 : 13;

    const __half* A  = g_probe[0] + (size_t)(b * S + it * BM) * V + st0 * 64;
    const __half* Bp = g_probe[1] + (size_t)(b * S + jt * BN) * V + st0 * 64;

    int lrow = t >> 1, lq = t & 1;               // loader: 128 rows x 2 thread-halves x 4 uint4
    const uint4* pa = (const uint4*)(A  + (size_t)lrow * V);
    const uint4* pb = (const uint4*)(Bp + (size_t)lrow * V);
    __half2 ra = g_rzh[b * S + it * BM + lrow];
    __half2 rb = g_rzh[BS + b * S + jt * BN + lrow];

    int tx = t & 15;               // col group (8 cols)
    int ty = t >> 4;               // row group (8 rows)

    uint4 ga[4], gb[4];
    float acc[8][8];
#pragma unroll
    for (int i = 0; i < 8; i++)
#pragma unroll
        for (int j = 0; j < 8; j++) acc[i][j] = 0.f;

    // prologue: stage 0 -> buf 0, prefetch stage 1 into regs
#pragma unroll
    for (int u = 0; u < 4; u++) { ga[u] = pa[lq * 4 + u]; gb[u] = pb[lq * 4 + u]; }
#pragma unroll
    for (int u = 0; u < 4; u++) {
        const __half2* ha = (const __half2*)&ga[u];
        const __half2* hb = (const __half2*)&gb[u];
#pragma unroll
        for (int j = 0; j < 4; j++) {
            sa2[0][(lq * 4 + u) * 4 + j][lrow] = __hmul2(ha[j], ra);
            sb2[0][(lq * 4 + u) * 4 + j][lrow] = __hmul2(hb[j], rb);
        }
    }
    if (1 < nst) {
#pragma unroll
        for (int u = 0; u < 4; u++) { ga[u] = pa[8 + lq * 4 + u]; gb[u] = pb[8 + lq * 4 + u]; }
    }
    __syncthreads();

    for (int s = 0; s < nst; s++) {
        int cur = s & 1, nxt = cur ^ 1;
        if (s + 1 < nst) {         // store regs (stage s+1) into other buffer
#pragma unroll
            for (int u = 0; u < 4; u++) {
                const __half2* ha = (const __half2*)&ga[u];
                const __half2* hb = (const __half2*)&gb[u];
#pragma unroll
                for (int j = 0; j < 4; j++) {
                    sa2[nxt][(lq * 4 + u) * 4 + j][lrow] = __hmul2(ha[j], ra);
                    sb2[nxt][(lq * 4 + u) * 4 + j][lrow] = __hmul2(hb[j], rb);
                }
            }
        }
        if (s + 2 < nst) {         // prefetch stage s+2 into regs
            int base = (s + 2) * 8;
#pragma unroll
            for (int u = 0; u < 4; u++) { ga[u] = pa[base + lq * 4 + u]; gb[u] = pb[base + lq * 4 + u]; }
        }

        __half2 hacc[8][8];
#pragma unroll
        for (int i = 0; i < 8; i++)
#pragma unroll
            for (int j = 0; j < 8; j++) hacc[i][j] = __float2half2_rn(0.f);

#pragma unroll 4
        for (int kk2 = 0; kk2 < BK2; kk2++) {
            float4 fa0 = *(const float4*)&sa2[cur][kk2][ty * 8];
            float4 fa1 = *(const float4*)&sa2[cur][kk2][ty * 8 + 4];
            float4 fb0 = *(const float4*)&sb2[cur][kk2][tx * 8];
            float4 fb1 = *(const float4*)&sb2[cur][kk2][tx * 8 + 4];
            __half2 a[8], c[8];
            *(float4*)&a[0] = fa0; *(float4*)&a[4] = fa1;
            *(float4*)&c[0] = fb0; *(float4*)&c[4] = fb1;
#pragma unroll
            for (int i = 0; i < 8; i++)
#pragma unroll
                for (int j = 0; j < 8; j++)
                    hacc[i][j] = __hadd2(hacc[i][j], __hmin2(a[i], c[j]));
        }
#pragma unroll
        for (int i = 0; i < 8; i++)
#pragma unroll
            for (int j = 0; j < 8; j++) {
                float2 f = __half22float2(hacc[i][j]);
                acc[i][j] += f.x + f.y;
            }
        __syncthreads();
    }

    float* out = g_part + (size_t)(b * KS + ks) * (S * S)
               + (it * BM + ty * 8) * S + jt * BN + tx * 8;
#pragma unroll
    for (int i = 0; i < 8; i++) {
        *(float4*)(out + i * S)     = make_float4(acc[i][0], acc[i][1], acc[i][2], acc[i][3]);
        *(float4*)(out + i * S + 4) = make_float4(acc[i][4], acc[i][5], acc[i][6], acc[i][7]);
    }
}

// ---------------- phase 3: K-split reduce -> W = 2 - 2*summin ----------------
__global__ void reduceW_kernel() {
    int idx = blockIdx.x * 256 + threadIdx.x;
    int b  = idx >> 16;
    int ij = idx & 65535;
    float s = 0.f;
#pragma unroll
    for (int ks = 0; ks < KS; ks++)
        s += g_part[(size_t)(b * KS + ks) * (S * S) + ij];
    g_W[idx] = 2.0f - s * INV2SCALE;
}

// ---------------- phase 4: Sinkhorn, P in smem (half2 storage, half2 scaling) ----------------
__global__ void __launch_bounds__(1024) sinkhorn_kernel() {
    extern __shared__ __align__(16) __half2 sP[];   // [256][128] half2 = 128 KB
    __shared__ float cpart[32][256];
    __shared__ float spart[4][256];
    __shared__ __align__(16) __half2 sch2[128];     // packed 1/colsum
    __shared__ float red[32];

    int b = blockIdx.x, t = threadIdx.x;
    int w = t >> 5, l = t & 31;
    const float* W = g_W + (size_t)b * (S * S);
    uint4* sPu = (uint4*)sP;

    float cp[8], rinv[8];
#pragma unroll
    for (int j = 0; j < 8; j++) cp[j] = 0.f;

    // init: e = exp(-10W), first row-normalize in fp32, then store half
#pragma unroll
    for (int r = 0; r < 8; r++) {
        int row = w * 8 + r;
        float4 a = ((const float4*)(W + row * 256))[2 * l];
        float4 c = ((const float4*)(W + row * 256))[2 * l + 1];
        float e[8];
        e[0] = __expf(-10.f * a.x); e[1] = __expf(-10.f * a.y);
        e[2] = __expf(-10.f * a.z); e[3] = __expf(-10.f * a.w);
        e[4] = __expf(-10.f * c.x); e[5] = __expf(-10.f * c.y);
        e[6] = __expf(-10.f * c.z); e[7] = __expf(-10.f * c.w);
        float rs = (e[0] + e[1]) + (e[2] + e[3]) + (e[4] + e[5]) + (e[6] + e[7]);
#pragma unroll
        for (int o = 16; o; o >>= 1) rs += __shfl_xor_sync(0xffffffffu, rs, o);
        float ri = 1.0f / rs;
        __half2 h[4];
#pragma unroll
        for (int j = 0; j < 4; j++) {
            float x0 = e[2 * j] * ri, x1 = e[2 * j + 1] * ri;
            cp[2 * j] += x0; cp[2 * j + 1] += x1;
            h[j] = __floats2half2_rn(x0, x1);
        }
        sPu[row * 32 + l] = *(uint4*)h;
    }

    for (int iter = 0; iter < 10; iter++) {
        // column-sum reduction from per-warp partials -> packed half2 inverse scales
        ((float4*)cpart[w])[2 * l]     = make_float4(cp[0], cp[1], cp[2], cp[3]);
        ((float4*)cpart[w])[2 * l + 1] = make_float4(cp[4], cp[5], cp[6], cp[7]);
        __syncthreads();
        {
            int c = t & 255, g = t >> 8;
            float s = 0.f;
#pragma unroll
            for (int k = 0; k < 8; k++) s += cpart[g * 8 + k][c];
            spart[g][c] = s;
        }
        __syncthreads();
        if (t < 128) {
            int c0 = 2 * t, c1 = 2 * t + 1;
            float s0 = spart[0][c0] + spart[1][c0] + spart[2][c0] + spart[3][c0];
            float s1 = spart[0][c1] + spart[1][c1] + spart[2][c1] + spart[3][c1];
            sch2[t] = __floats2half2_rn(1.0f / s0, 1.0f / s1);
        }
        __syncthreads();

        // col multiply (HMUL2) + row sums (fp32)
        uint4 sv = ((const uint4*)sch2)[l];
        const __half2* ss = (const __half2*)&sv;
#pragma unroll
        for (int r = 0; r < 8; r++) {
            int row = w * 8 + r;
            uint4 pu = sPu[row * 32 + l];
            __half2* ph = (__half2*)&pu;
            ph[0] = __hmul2(ph[0], ss[0]);
            ph[1] = __hmul2(ph[1], ss[1]);
            ph[2] = __hmul2(ph[2], ss[2]);
            ph[3] = __hmul2(ph[3], ss[3]);
            sPu[row * 32 + l] = pu;
            float2 f0 = __half22float2(ph[0]);
            float2 f1 = __half22float2(ph[1]);
            float2 f2 = __half22float2(ph[2]);
            float2 f3 = __half22float2(ph[3]);
            float rs = (f0.x + f0.y) + (f1.x + f1.y) + (f2.x + f2.y) + (f3.x + f3.y);
#pragma unroll
            for (int o = 16; o; o >>= 1) rs += __shfl_xor_sync(0xffffffffu, rs, o);
            rinv[r] = 1.0f / rs;
        }

        if (iter < 9) {
            // row multiply (HMUL2) + next col partials (fp32)
#pragma unroll
            for (int j = 0; j < 8; j++) cp[j] = 0.f;
#pragma unroll
            for (int r = 0; r < 8; r++) {
                int row = w * 8 + r;
                uint4 pu = sPu[row * 32 + l];
                __half2* ph = (__half2*)&pu;
                __half2 rih = __float2half2_rn(rinv[r]);
                ph[0] = __hmul2(ph[0], rih);
                ph[1] = __hmul2(ph[1], rih);
                ph[2] = __hmul2(ph[2], rih);
                ph[3] = __hmul2(ph[3], rih);
                sPu[row * 32 + l] = pu;
                float2 f0 = __half22float2(ph[0]);
                float2 f1 = __half22float2(ph[1]);
                float2 f2 = __half22float2(ph[2]);
                float2 f3 = __half22float2(ph[3]);
                cp[0] += f0.x; cp[1] += f0.y; cp[2] += f1.x; cp[3] += f1.y;
                cp[4] += f2.x; cp[5] += f2.y; cp[6] += f3.x; cp[7] += f3.y;
            }
        }
        __syncthreads();
    }

    // loss = sum(P * W)
    float acc = 0.f;
#pragma unroll
    for (int r = 0; r < 8; r++) {
        int row = w * 8 + r;
        uint4 pu = sPu[row * 32 + l];
        __half2* ph = (__half2*)&pu;
        float4 a = ((const float4*)(W + row * 256))[2 * l];
        float4 c = ((const float4*)(W + row * 256))[2 * l + 1];
        float2 f0 = __half22float2(ph[0]);
        float2 f1 = __half22float2(ph[1]);
        float2 f2 = __half22float2(ph[2]);
        float2 f3 = __half22float2(ph[3]);
        acc += f0.x * a.x + f0.y * a.y + f1.x * a.z + f1.y * a.w
             + f2.x * c.x + f2.y * c.y + f3.x * c.z + f3.y * c.w;
    }
#pragma unroll
    for (int o = 16; o; o >>= 1) acc += __shfl_xor_sync(0xffffffffu, acc, o);
    if (l == 0) red[w] = acc;
    __syncthreads();
    if (t == 0) {
        float s = 0.f;
        for (int k = 0; k < 32; k++) s += red[k];
        g_loss[b] = s;
    }
}

__global__ void finalize_kernel(float* out) {
    out[0] = 0.001f * (g_loss[0] + g_loss[1] + g_loss[2] + g_loss[3]);
}

// ---------------- launch ----------------
extern "C" void kernel_launch(void* const* d_in, const int* in_sizes, int n_in,
                              void* d_out, int out_size) {
    const float* ys = (const float*)d_in[0];
    const float* yt = (const float*)d_in[1];

    cudaFuncSetAttribute(cdist_kernel, cudaFuncAttributeMaxDynamicSharedMemorySize, CD_SMEM);
    cudaFuncSetAttribute(sinkhorn_kernel, cudaFuncAttributeMaxDynamicSharedMemorySize, SINK_SMEM);

    stats_kernel<<<dim3(BS, 2), 256>>>(ys, yt);
    cdist_kernel<<<dim3(4, KS, B), 256, CD_SMEM>>>();
    reduceW_kernel<<<dim3(B * S * S / 256), 256>>>();
    sinkhorn_kernel<<<B, 1024, SINK_SMEM>>>();
    finalize_kernel<<<1, 1>>>((float*)d_out);
}

// round 8
// speedup vs baseline: 2.3731x; 1.0038x over previous
#include <cuda_runtime.h>
#include <cuda_fp16.h>
#include <math.h>

// Fixed shapes: y_s, y_t : [4, 256, 32000] fp32
#define B 4
#define S 256
#define V 32000
#define BS (B * S)
#define KS 37                      // uneven K-split: 19 chunks of 14 stages, 18 of 13 (x64 halfs)
#define BM 128
#define BN 128
#define BK2 32                     // half2 per stage = 64 halfs
#define SCALE 8192.0f
#define INV2SCALE (2.0f / SCALE)

#define CD_SMEM (2 * 2 * BK2 * (BM + 4) * (int)sizeof(__half2))   // 67584
#define SINK_SMEM (S * (S / 2) * (int)sizeof(__half2))            // 131072

// ---------------- static device scratch ----------------
__device__ __half g_probe[2][BS * V];          // UNNORMALIZED exp(y/2) as half (131 MB)
__device__ __half2 g_rzh[2 * BS];              // per-row SCALE/Z as half2
__device__ float g_part[B * KS * S * S];       // K-split partial scaled sum-of-min
__device__ float g_W[B * S * S];
__device__ float g_loss[B];

// ---------------- phase 1 (fused): exp + row-sum stats, single pass over y ----------------
__global__ void stats_kernel(const float* __restrict__ ys, const float* __restrict__ yt) {
    int row = blockIdx.x;
    int tensor = blockIdx.y;
    const float* y = (tensor ? yt : ys) + (size_t)row * V;
    __half* e = g_probe[tensor] + (size_t)row * V;
    int tid = threadIdx.x;

    float Z = 0.f;
    for (int f = tid; f < V / 4; f += 256) {
        float4 v = ((const float4*)y)[f];
        float e0 = __expf(v.x * 0.5f);
        float e1 = __expf(v.y * 0.5f);
        float e2 = __expf(v.z * 0.5f);
        float e3 = __expf(v.w * 0.5f);
        Z += (e0 + e1) + (e2 + e3);
        __half2 h[2];
        h[0] = __floats2half2_rn(e0, e1);
        h[1] = __floats2half2_rn(e2, e3);
        ((uint2*)e)[f] = *(uint2*)h;
    }

    __shared__ float sz[256];
    sz[tid] = Z;
    __syncthreads();
    for (int s = 128; s > 0; s >>= 1) {
        if (tid < s) sz[tid] += sz[tid + s];
        __syncthreads();
    }
    if (tid == 0) {
        float r = SCALE / sz[0];
        g_rzh[tensor * BS + row] = __floats2half2_rn(r, r);
    }
}

// ---------------- phase 2: half2 sum-of-min "GEMM", 128x128 tile, 512 thr, 8x4 micro ----------------
__global__ void __launch_bounds__(512, 1) cdist_kernel() {
    extern __shared__ __align__(16) __half2 dyn[];
    typedef __half2 ST[BK2][BM + 4];
    ST* sa2 = (ST*)dyn;                         // [2][BK2][BM+4]
    ST* sb2 = (ST*)(dyn + 2 * BK2 * (BM + 4));  // [2][BK2][BN+4]

    int t  = threadIdx.x;
    int it = blockIdx.x >> 1;      // 0..1
    int jt = blockIdx.x & 1;       // 0..1
    int ks = blockIdx.y;           // 0..36
    int b  = blockIdx.z;

    int st0 = (ks < 19) ? 14 * ks : 13 * ks + 19;   // chunk start in 64-half units
    int nst = (ks < 19) ? 14 : 13;

    const __half* A  = g_probe[0] + (size_t)(b * S + it * BM) * V + st0 * 64;
    const __half* Bp = g_probe[1] + (size_t)(b * S + jt * BN) * V + st0 * 64;

    int lrow = t >> 2, lq = t & 3;               // loader: 128 rows x 4 threads x 2 uint4
    const uint4* pa = (const uint4*)(A  + (size_t)lrow * V);
    const uint4* pb = (const uint4*)(Bp + (size_t)lrow * V);
    __half2 ra = g_rzh[b * S + it * BM + lrow];
    __half2 rb = g_rzh[BS + b * S + jt * BN + lrow];

    int tx = t & 31;               // col group (4 cols) -> conflict-free 16B-stride LDS
    int ty = t >> 5;               // row group (8 rows) -> broadcast LDS

    uint4 ga[2], gb[2];
    float acc[8][4];
#pragma unroll
    for (int i = 0; i < 8; i++)
#pragma unroll
        for (int j = 0; j < 4; j++) acc[i][j] = 0.f;

    // prologue: stage 0 -> buf 0, prefetch stage 1 into regs
#pragma unroll
    for (int u = 0; u < 2; u++) { ga[u] = pa[lq * 2 + u]; gb[u] = pb[lq * 2 + u]; }
#pragma unroll
    for (int u = 0; u < 2; u++) {
        const __half2* ha = (const __half2*)&ga[u];
        const __half2* hb = (const __half2*)&gb[u];
#pragma unroll
        for (int j = 0; j < 4; j++) {
            sa2[0][(lq * 2 + u) * 4 + j][lrow] = __hmul2(ha[j], ra);
            sb2[0][(lq * 2 + u) * 4 + j][lrow] = __hmul2(hb[j], rb);
        }
    }
    if (1 < nst) {
#pragma unroll
        for (int u = 0; u < 2; u++) { ga[u] = pa[8 + lq * 2 + u]; gb[u] = pb[8 + lq * 2 + u]; }
    }
    __syncthreads();

    for (int s = 0; s < nst; s++) {
        int cur = s & 1, nxt = cur ^ 1;
        if (s + 1 < nst) {         // store regs (stage s+1) into other buffer
#pragma unroll
            for (int u = 0; u < 2; u++) {
                const __half2* ha = (const __half2*)&ga[u];
                const __half2* hb = (const __half2*)&gb[u];
#pragma unroll
                for (int j = 0; j < 4; j++) {
                    sa2[nxt][(lq * 2 + u) * 4 + j][lrow] = __hmul2(ha[j], ra);
                    sb2[nxt][(lq * 2 + u) * 4 + j][lrow] = __hmul2(hb[j], rb);
                }
            }
        }
        if (s + 2 < nst) {         // prefetch stage s+2 into regs
            int base = (s + 2) * 8;
#pragma unroll
            for (int u = 0; u < 2; u++) { ga[u] = pa[base + lq * 2 + u]; gb[u] = pb[base + lq * 2 + u]; }
        }

        __half2 hacc[8][4];
#pragma unroll
        for (int i = 0; i < 8; i++)
#pragma unroll
            for (int j = 0; j < 4; j++) hacc[i][j] = __float2half2_rn(0.f);

#pragma unroll 8
        for (int kk2 = 0; kk2 < BK2; kk2++) {
            float4 fa0 = *(const float4*)&sa2[cur][kk2][ty * 8];
            float4 fa1 = *(const float4*)&sa2[cur][kk2][ty * 8 + 4];
            float4 fb  = *(const float4*)&sb2[cur][kk2][tx * 4];
            __half2 a[8], c[4];
            *(float4*)&a[0] = fa0; *(float4*)&a[4] = fa1;
            *(float4*)&c[0] = fb;
#pragma unroll
            for (int i = 0; i < 8; i++)
#pragma unroll
                for (int j = 0; j < 4; j++)
                    hacc[i][j] = __hadd2(hacc[i][j], __hmin2(a[i], c[j]));
        }
#pragma unroll
        for (int i = 0; i < 8; i++)
#pragma unroll
            for (int j = 0; j < 4; j++) {
                float2 f = __half22float2(hacc[i][j]);
                acc[i][j] += f.x + f.y;
            }
        __syncthreads();
    }

    float* out = g_part + (size_t)(b * KS + ks) * (S * S)
               + (it * BM + ty * 8) * S + jt * BN + tx * 4;
#pragma unroll
    for (int i = 0; i < 8; i++)
        *(float4*)(out + i * S) = make_float4(acc[i][0], acc[i][1], acc[i][2], acc[i][3]);
}

// ---------------- phase 3: K-split reduce -> W = 2 - 2*summin ----------------
__global__ void reduceW_kernel() {
    int idx = blockIdx.x * 256 + threadIdx.x;
    int b  = idx >> 16;
    int ij = idx & 65535;
    float s = 0.f;
#pragma unroll
    for (int ks = 0; ks < KS; ks++)
        s += g_part[(size_t)(b * KS + ks) * (S * S) + ij];
    g_W[idx] = 2.0f - s * INV2SCALE;
}

// ---------------- phase 4: Sinkhorn, P in smem (half2 storage, fp32 math) ----------------
__global__ void __launch_bounds__(1024) sinkhorn_kernel() {
    extern __shared__ __align__(16) __half2 sP[];   // [256][128] half2 = 128 KB
    __shared__ float cpart[32][256];
    __shared__ float spart[4][256];
    __shared__ float scf[256];
    __shared__ float red[32];

    int b = blockIdx.x, t = threadIdx.x;
    int w = t >> 5, l = t & 31;
    const float* W = g_W + (size_t)b * (S * S);
    uint4* sPu = (uint4*)sP;

    float cp[8], rinv[8];
#pragma unroll
    for (int j = 0; j < 8; j++) cp[j] = 0.f;

    // init: e = exp(-10W), first row-normalize in fp32, then store half
#pragma unroll
    for (int r = 0; r < 8; r++) {
        int row = w * 8 + r;
        float4 a = ((const float4*)(W + row * 256))[2 * l];
        float4 c = ((const float4*)(W + row * 256))[2 * l + 1];
        float e[8];
        e[0] = __expf(-10.f * a.x); e[1] = __expf(-10.f * a.y);
        e[2] = __expf(-10.f * a.z); e[3] = __expf(-10.f * a.w);
        e[4] = __expf(-10.f * c.x); e[5] = __expf(-10.f * c.y);
        e[6] = __expf(-10.f * c.z); e[7] = __expf(-10.f * c.w);
        float rs = (e[0] + e[1]) + (e[2] + e[3]) + (e[4] + e[5]) + (e[6] + e[7]);
#pragma unroll
        for (int o = 16; o; o >>= 1) rs += __shfl_xor_sync(0xffffffffu, rs, o);
        float ri = 1.0f / rs;
        __half2 h[4];
#pragma unroll
        for (int j = 0; j < 4; j++) {
            float x0 = e[2 * j] * ri, x1 = e[2 * j + 1] * ri;
            cp[2 * j] += x0; cp[2 * j + 1] += x1;
            h[j] = __floats2half2_rn(x0, x1);
        }
        sPu[row * 32 + l] = *(uint4*)h;
    }

    for (int iter = 0; iter < 10; iter++) {
        // column-sum reduction from per-warp partials
        ((float4*)cpart[w])[2 * l]     = make_float4(cp[0], cp[1], cp[2], cp[3]);
        ((float4*)cpart[w])[2 * l + 1] = make_float4(cp[4], cp[5], cp[6], cp[7]);
        __syncthreads();
        {
            int c = t & 255, g = t >> 8;
            float s = 0.f;
#pragma unroll
            for (int k = 0; k < 8; k++) s += cpart[g * 8 + k][c];
            spart[g][c] = s;
        }
        __syncthreads();
        if (t < 256)
            scf[t] = 1.0f / (spart[0][t] + spart[1][t] + spart[2][t] + spart[3][t]);
        __syncthreads();

        // col multiply (fp32 math, half storage) + row sums
        float4 s0 = ((float4*)scf)[2 * l];
        float4 s1 = ((float4*)scf)[2 * l + 1];
#pragma unroll
        for (int r = 0; r < 8; r++) {
            int row = w * 8 + r;
            uint4 pu = sPu[row * 32 + l];
            __half2* ph = (__half2*)&pu;
            float2 f0 = __half22float2(ph[0]);
            float2 f1 = __half22float2(ph[1]);
            float2 f2 = __half22float2(ph[2]);
            float2 f3 = __half22float2(ph[3]);
            f0.x *= s0.x; f0.y *= s0.y; f1.x *= s0.z; f1.y *= s0.w;
            f2.x *= s1.x; f2.y *= s1.y; f3.x *= s1.z; f3.y *= s1.w;
            ph[0] = __floats2half2_rn(f0.x, f0.y);
            ph[1] = __floats2half2_rn(f1.x, f1.y);
            ph[2] = __floats2half2_rn(f2.x, f2.y);
            ph[3] = __floats2half2_rn(f3.x, f3.y);
            sPu[row * 32 + l] = pu;
            float rs = (f0.x + f0.y) + (f1.x + f1.y) + (f2.x + f2.y) + (f3.x + f3.y);
#pragma unroll
            for (int o = 16; o; o >>= 1) rs += __shfl_xor_sync(0xffffffffu, rs, o);
            rinv[r] = 1.0f / rs;
        }

        if (iter < 9) {
            // row multiply + next col partials
#pragma unroll
            for (int j = 0; j < 8; j++) cp[j] = 0.f;
#pragma unroll
            for (int r = 0; r < 8; r++) {
                int row = w * 8 + r;
                uint4 pu = sPu[row * 32 + l];
                __half2* ph = (__half2*)&pu;
                float ri = rinv[r];
                float2 f0 = __half22float2(ph[0]);
                float2 f1 = __half22float2(ph[1]);
                float2 f2 = __half22float2(ph[2]);
                float2 f3 = __half22float2(ph[3]);
                f0.x *= ri; f0.y *= ri; f1.x *= ri; f1.y *= ri;
                f2.x *= ri; f2.y *= ri; f3.x *= ri; f3.y *= ri;
                cp[0] += f0.x; cp[1] += f0.y; cp[2] += f1.x; cp[3] += f1.y;
                cp[4] += f2.x; cp[5] += f2.y; cp[6] += f3.x; cp[7] += f3.y;
                ph[0] = __floats2half2_rn(f0.x, f0.y);
                ph[1] = __floats2half2_rn(f1.x, f1.y);
                ph[2] = __floats2half2_rn(f2.x, f2.y);
                ph[3] = __floats2half2_rn(f3.x, f3.y);
                sPu[row * 32 + l] = pu;
            }
        }
        __syncthreads();
    }

    // loss = sum(P * W)
    float acc = 0.f;
#pragma unroll
    for (int r = 0; r < 8; r++) {
        int row = w * 8 + r;
        uint4 pu = sPu[row * 32 + l];
        __half2* ph = (__half2*)&pu;
        float4 a = ((const float4*)(W + row * 256))[2 * l];
        float4 c = ((const float4*)(W + row * 256))[2 * l + 1];
        float2 f0 = __half22float2(ph[0]);
        float2 f1 = __half22float2(ph[1]);
        float2 f2 = __half22float2(ph[2]);
        float2 f3 = __half22float2(ph[3]);
        acc += f0.x * a.x + f0.y * a.y + f1.x * a.z + f1.y * a.w
             + f2.x * c.x + f2.y * c.y + f3.x * c.z + f3.y * c.w;
    }
#pragma unroll
    for (int o = 16; o; o >>= 1) acc += __shfl_xor_sync(0xffffffffu, acc, o);
    if (l == 0) red[w] = acc;
    __syncthreads();
    if (t == 0) {
        float s = 0.f;
        for (int k = 0; k < 32; k++) s += red[k];
        g_loss[b] = s;
    }
}

__global__ void finalize_kernel(float* out) {
    out[0] = 0.001f * (g_loss[0] + g_loss[1] + g_loss[2] + g_loss[3]);
}

// ---------------- launch ----------------
extern "C" void kernel_launch(void* const* d_in, const int* in_sizes, int n_in,
                              void* d_out, int out_size) {
    const float* ys = (const float*)d_in[0];
    const float* yt = (const float*)d_in[1];

    cudaFuncSetAttribute(cdist_kernel, cudaFuncAttributeMaxDynamicSharedMemorySize, CD_SMEM);
    cudaFuncSetAttribute(sinkhorn_kernel, cudaFuncAttributeMaxDynamicSharedMemorySize, SINK_SMEM);

    stats_kernel<<<dim3(BS, 2), 256>>>(ys, yt);
    cdist_kernel<<<dim3(4, KS, B), 512, CD_SMEM>>>();
    reduceW_kernel<<<dim3(B * S * S / 256), 256>>>();
    sinkhorn_kernel<<<B, 1024, SINK_SMEM>>>();
    finalize_kernel<<<1, 1>>>((float*)d_out);
}